// round 5
// baseline (speedup 1.0000x reference)
#include <cuda_runtime.h>

#define Bsz 2
#define Nn  4096
#define Cc  192
#define Hh  8
#define Dd  24
#define JCH 32                  // j-rows per task
#define NCH 128                 // chunks per batch
#define NTASK (Bsz * NCH)       // 256
#define NBLK 256
#define NT   512

// Scratch (__device__ globals; no allocations allowed)
__device__ float g_wksum[Hh * Cc];
__device__ __align__(16) float g_xwpart[NTASK * Hh * Cc];
__device__ float g_zpart[Bsz * Hh * NCH];
__device__ float g_ov[Bsz * Cc];
__device__ __align__(16) float g_yrow[Bsz * Cc];

// Flags (reset by k_pre every replay; graph edge orders k_pre before fused)
__device__ unsigned int g_ac_done = 0;
__device__ unsigned int g_d_done  = 0;
__device__ unsigned int g_ready   = 0;

// ---------------------------------------------------------------------------
// Prelude: wk_sum[h,c] = sum_d W_k[(C+h*D+d), c]; reset flags.
// ---------------------------------------------------------------------------
__global__ void k_pre(const float* __restrict__ Wqkv) {
    int gid = blockIdx.x * 512 + threadIdx.x;      // 0..1535
    if (gid == 0) { g_ac_done = 0; g_d_done = 0; g_ready = 0; }
    int h = gid / Cc, c = gid - h * Cc;
    const float* base = Wqkv + (size_t)(Cc + h * Dd) * Cc + c;
    float s = 0.f;
#pragma unroll
    for (int d = 0; d < Dd; d++) s += base[(size_t)d * Cc];
    g_wksum[gid] = s;
}

// ---------------------------------------------------------------------------
__global__ __launch_bounds__(NT, 2)
void fused_kernel(const float* __restrict__ x,
                  const float* __restrict__ Wqkv,
                  const float* __restrict__ Wproj,
                  const float* __restrict__ bproj,
                  const float* __restrict__ scale,
                  float4* __restrict__ out) {
    __shared__ float s_ws[Hh * Cc];                       // 1536
    __shared__ float s_e[Hh * JCH];                       // 256
    __shared__ __align__(16) float s_comb[Hh * Cc];       // 1536 (AC combine / D staging)
    __shared__ __align__(16) float s_xw[Cc];
    __shared__ float s_invz;
    __shared__ __align__(16) float s_y[Bsz * Cc];         // 384
    __shared__ unsigned int s_rank;

    const int tid  = threadIdx.x;
    const int bid  = blockIdx.x;
    const int warp = tid >> 5;
    const int lane = tid & 31;

    // =============== Phase AC: e (block-local) -> xw partial + Z partial ===============
    {
        const int b     = bid >> 7;
        const int chunk = bid & 127;
        const int j0    = chunk * JCH;

        for (int i = tid; i < Hh * Cc; i += NT) s_ws[i] = g_wksum[i];
        __syncthreads();

        const float sc = __ldg(scale);
#pragma unroll
        for (int r = 0; r < 2; r++) {
            const int jj = warp * 2 + r;
            const float* xr = x + (size_t)(b * Nn + j0 + jj) * Cc;
            float xv[6];
#pragma unroll
            for (int i = 0; i < 6; i++) xv[i] = xr[lane + 32 * i];
#pragma unroll
            for (int h = 0; h < Hh; h++) {
                float p = 0.f;
#pragma unroll
                for (int i = 0; i < 6; i++) p += xv[i] * s_ws[h * Cc + lane + 32 * i];
#pragma unroll
                for (int o = 16; o > 0; o >>= 1) p += __shfl_down_sync(0xffffffffu, p, o);
                if (lane == 0) s_e[h * JCH + jj] = __expf(p * sc);
            }
        }
        __syncthreads();

        const int jg = tid / Cc;
        const int c  = tid - jg * Cc;
        float acc[Hh];
#pragma unroll
        for (int h = 0; h < Hh; h++) acc[h] = 0.f;

        if (tid < 2 * Cc) {
            const float* xp = x + ((size_t)(b * Nn + j0 + jg * 16)) * Cc + c;
#pragma unroll 8
            for (int q = 0; q < 16; q++) {
                float xv = xp[(size_t)q * Cc];
                int wj = jg * 16 + q;
#pragma unroll
                for (int h = 0; h < Hh; h++) acc[h] += s_e[h * JCH + wj] * xv;
            }
        } else if (warp >= 12) {                   // tids 384..511: Z partials
            int h = (warp - 12) * 2 + (lane >> 4);
            int l = lane & 15;
            float z = s_e[h * JCH + l] + s_e[h * JCH + 16 + l];
#pragma unroll
            for (int o = 8; o > 0; o >>= 1) z += __shfl_xor_sync(0xffffffffu, z, o);
            if (l == 0) g_zpart[(b * Hh + h) * NCH + chunk] = z;
        }
        __syncthreads();
        if (jg == 1) {
#pragma unroll
            for (int h = 0; h < Hh; h++) s_comb[h * Cc + c] = acc[h];
        }
        __syncthreads();
        if (jg == 0) {
#pragma unroll
            for (int h = 0; h < Hh; h++) s_comb[h * Cc + c] += acc[h];
        }
        __syncthreads();
        if (tid < 384)
            ((float4*)g_xwpart)[bid * 384 + tid] = ((const float4*)s_comb)[tid];

        __threadfence();
        __syncthreads();
        if (tid == 0) atomicAdd(&g_ac_done, 1u);
    }

    // =============== Phase D: 16 blocks (b,h): wait AC -> reduce -> Vproj -> ov ===============
    if (bid < Bsz * Hh) {
        const int b = bid >> 3, h = bid & 7;

        if (tid == 0) {
            volatile unsigned int* p = &g_ac_done;
            while (*p < (unsigned)NBLK) __nanosleep(64);
        }
        __syncthreads();
        __threadfence();

        if (tid < 384) {                           // (slice 0..7) x (f4-col 0..47)
            const int col = tid % 48, slice = tid / 48;
            const float4* p = (const float4*)g_xwpart;
            int base = (b * NCH + slice * 16) * 384 + h * 48 + col;
            float4 s = make_float4(0.f, 0.f, 0.f, 0.f);
#pragma unroll
            for (int k = 0; k < 16; k++) {
                float4 v = p[base + k * 384];
                s.x += v.x; s.y += v.y; s.z += v.z; s.w += v.w;
            }
            ((float4*)s_comb)[tid] = s;
        }
        if (warp == 15) {                          // Z reduce (128 partials)
            const float* zp = g_zpart + (b * Hh + h) * NCH;
            float z = zp[lane] + zp[lane + 32] + zp[lane + 64] + zp[lane + 96];
#pragma unroll
            for (int o = 16; o > 0; o >>= 1) z += __shfl_xor_sync(0xffffffffu, z, o);
            if (lane == 0) s_invz = 1.f / z;
        }
        __syncthreads();
        if (tid < 48) {
            float4 a = make_float4(0.f, 0.f, 0.f, 0.f);
#pragma unroll
            for (int sl = 0; sl < 8; sl++) {
                float4 v = ((const float4*)s_comb)[sl * 48 + tid];
                a.x += v.x; a.y += v.y; a.z += v.z; a.w += v.w;
            }
            ((float4*)s_xw)[tid] = a;
        }
        __syncthreads();

        // V projection: warps 0..11, 2 d's each; apply invZ
        if (warp < 12) {
#pragma unroll
            for (int dd = 0; dd < 2; dd++) {
                int d = warp * 2 + dd;
                const float* wv = Wqkv + (size_t)(2 * Cc + h * Dd + d) * Cc;
                float p = 0.f;
#pragma unroll
                for (int i = 0; i < 6; i++) p += s_xw[lane + 32 * i] * wv[lane + 32 * i];
#pragma unroll
                for (int o = 16; o > 0; o >>= 1) p += __shfl_down_sync(0xffffffffu, p, o);
                if (lane == 0) g_ov[b * Cc + h * Dd + d] = p * s_invz;
            }
        }
        __threadfence();
        __syncthreads();
        if (tid == 0) s_rank = atomicAdd(&g_d_done, 1u);
        __syncthreads();

        // Last D block: final projection (pure function of g_ov => deterministic)
        if (s_rank == (unsigned)(Bsz * Hh - 1)) {
            __threadfence();
            if (tid < Bsz * Cc) {
                const int b2 = tid / Cc, t = tid - b2 * Cc;
                const float4* wp = (const float4*)(Wproj + (size_t)t * Cc);
                const float4* ov = (const float4*)(g_ov + b2 * Cc);
                float s = bproj[t];
#pragma unroll
                for (int q = 0; q < 48; q++) {
                    float4 w4 = wp[q], o4 = ov[q];
                    s += w4.x * o4.x + w4.y * o4.y + w4.z * o4.z + w4.w * o4.w;
                }
                g_yrow[tid] = s;
            }
            __threadfence();
            __syncthreads();
            if (tid == 0) atomicExch(&g_ready, 1u);
        }
    }

    // =============== Phase E: wait ready -> broadcast ===============
    {
        if (tid == 0) {
            volatile unsigned int* p = &g_ready;
            while (*p == 0u) __nanosleep(64);
        }
        __syncthreads();
        __threadfence();
        if (tid < Bsz * 48)
            ((float4*)s_y)[tid] = ((const float4*)g_yrow)[tid];
        __syncthreads();
        const float4* sy4 = (const float4*)s_y;
        const int base = bid * 1536;               // 256 * 1536 = 393216 float4
#pragma unroll
        for (int k = 0; k < 3; k++) {
            int g   = base + k * NT + tid;
            int r   = g % 48;
            int b   = (g >= Nn * 48) ? 1 : 0;
            out[g] = sy4[b * 48 + r];
        }
    }
}

extern "C" void kernel_launch(void* const* d_in, const int* in_sizes, int n_in,
                              void* d_out, int out_size) {
    const float* x     = (const float*)d_in[0];
    const float* Wqkv  = (const float*)d_in[1];
    const float* Wproj = (const float*)d_in[2];
    const float* bproj = (const float*)d_in[3];
    const float* scale = (const float*)d_in[4];

    k_pre<<<3, 512>>>(Wqkv);
    fused_kernel<<<NBLK, NT>>>(x, Wqkv, Wproj, bproj, scale, (float4*)d_out);
}

// round 6
// speedup vs baseline: 1.3741x; 1.3741x over previous
#include <cuda_runtime.h>

#define Bsz 2
#define Nn  4096
#define Cc  192
#define Hh  8
#define Dd  24
#define JCH 64                  // j-rows per task (one block per SM, uniform)
#define NCH 64                  // chunks per batch
#define NTASK (Bsz * NCH)       // 128
#define NBLK 128
#define NT   512

#define FPSCALE 4194304.0f      // 2^22
#define FPINV   (1.0f / 4194304.0f)

// Scratch (__device__ globals; no allocations allowed)
__device__ float g_wksum[Hh * Cc];
__device__ __align__(16) float g_xwpart[NTASK * Hh * Cc];   // 128*1536
__device__ float g_zpart[Bsz * Hh * NCH];                   // 16*64
__device__ unsigned long long g_yfp[Bsz * Cc];

// Grid barrier (zero-init; count self-resets, gen monotonic => graph-replay safe)
__device__ unsigned int g_bar_count = 0;
__device__ unsigned int g_bar_gen   = 0;

__device__ __forceinline__ void grid_sync() {
    __threadfence();
    __syncthreads();
    if (threadIdx.x == 0) {
        volatile unsigned int* vgen = &g_bar_gen;
        unsigned int g0 = *vgen;
        if (atomicAdd(&g_bar_count, 1u) == (unsigned)(NBLK - 1)) {
            atomicExch(&g_bar_count, 0u);
            __threadfence();
            atomicAdd(&g_bar_gen, 1u);
        } else {
            while (*vgen == g0) __nanosleep(32);
        }
    }
    __syncthreads();
    __threadfence();
}

// ---------------------------------------------------------------------------
// Prelude: wk_sum[h,c] = sum_d W_k[(C+h*D+d), c]; zero fixed-point accumulator.
// ---------------------------------------------------------------------------
__global__ void k_pre(const float* __restrict__ Wqkv) {
    int gid = blockIdx.x * 512 + threadIdx.x;      // 0..1535
    if (gid < Bsz * Cc) g_yfp[gid] = 0ull;
    int h = gid / Cc, c = gid - h * Cc;
    const float* base = Wqkv + (size_t)(Cc + h * Dd) * Cc + c;
    float s = 0.f;
#pragma unroll
    for (int d = 0; d < Dd; d++) s += base[(size_t)d * Cc];
    g_wksum[gid] = s;
}

// ---------------------------------------------------------------------------
__global__ __launch_bounds__(NT, 1)
void fused_kernel(const float* __restrict__ x,
                  const float* __restrict__ Wqkv,
                  const float* __restrict__ Wproj,
                  const float* __restrict__ bproj,
                  const float* __restrict__ scale,
                  float4* __restrict__ out) {
    __shared__ __align__(16) float s_ws[Hh * Cc];         // 1536
    __shared__ float s_e[Hh * JCH];                       // 512
    __shared__ __align__(16) float s_comb[Hh * Cc];       // 1536 (AC combine / D staging)
    __shared__ __align__(16) float s_xw[Cc];
    __shared__ float s_invz;
    __shared__ __align__(16) float s_y[Bsz * Cc];         // 384

    const int tid  = threadIdx.x;
    const int bid  = blockIdx.x;
    const int warp = tid >> 5;
    const int lane = tid & 31;

    // =============== Phase AC: e (block-local) -> xw partial + Z partial ===============
    {
        const int b     = bid >> 6;                // 64 chunks per batch
        const int chunk = bid & 63;
        const int j0    = chunk * JCH;

        if (tid < 384) ((float4*)s_ws)[tid] = ((const float4*)g_wksum)[tid];
        __syncthreads();

        const float sc = __ldg(scale);
        // e for 64 rows: 16 warps x 4 rows
#pragma unroll
        for (int r = 0; r < 4; r++) {
            const int jj = warp * 4 + r;
            const float* xr = x + (size_t)(b * Nn + j0 + jj) * Cc;
            float xv[6];
#pragma unroll
            for (int i = 0; i < 6; i++) xv[i] = xr[lane + 32 * i];
#pragma unroll
            for (int h = 0; h < Hh; h++) {
                float p = 0.f;
#pragma unroll
                for (int i = 0; i < 6; i++) p += xv[i] * s_ws[h * Cc + lane + 32 * i];
#pragma unroll
                for (int o = 16; o > 0; o >>= 1) p += __shfl_down_sync(0xffffffffu, p, o);
                if (lane == 0) s_e[h * JCH + jj] = __expf(p * sc);
            }
        }
        __syncthreads();

        // xw partial: threads 0..383 = (jg, c) over 32 rows each; Z: warps 12..15
        const int jg = tid / Cc;
        const int c  = tid - jg * Cc;
        float acc[Hh];
#pragma unroll
        for (int h = 0; h < Hh; h++) acc[h] = 0.f;

        if (tid < 2 * Cc) {
            const float* xp = x + ((size_t)(b * Nn + j0 + jg * 32)) * Cc + c;
#pragma unroll 8
            for (int q = 0; q < 32; q++) {
                float xv = xp[(size_t)q * Cc];     // L1-hot (read in e phase)
                int wj = jg * 32 + q;
#pragma unroll
                for (int h = 0; h < Hh; h++) acc[h] += s_e[h * JCH + wj] * xv;
            }
        } else if (warp >= 12) {                   // tids 384..511: Z partials
            int h = (warp - 12) * 2 + (lane >> 4);
            int l = lane & 15;
            const float* eh = s_e + h * JCH;
            float z = eh[l] + eh[16 + l] + eh[32 + l] + eh[48 + l];
#pragma unroll
            for (int o = 8; o > 0; o >>= 1) z += __shfl_xor_sync(0xffffffffu, z, o);
            if (l == 0) g_zpart[(b * Hh + h) * NCH + chunk] = z;
        }
        __syncthreads();
        if (jg == 1) {
#pragma unroll
            for (int h = 0; h < Hh; h++) s_comb[h * Cc + c] = acc[h];
        }
        __syncthreads();
        if (jg == 0) {
#pragma unroll
            for (int h = 0; h < Hh; h++) s_comb[h * Cc + c] += acc[h];
        }
        __syncthreads();
        if (tid < 384)
            ((float4*)g_xwpart)[bid * 384 + tid] = ((const float4*)s_comb)[tid];
    }
    grid_sync();

    // =============== Phase D: 16 blocks (b,h): reduce + Vproj + yfp atomics ===============
    if (bid < Bsz * Hh) {
        const int b = bid >> 3, h = bid & 7;

        if (tid < 384) {                           // (slice 0..7) x (f4-col 0..47)
            const int col = tid % 48, slice = tid / 48;
            const float4* p = (const float4*)g_xwpart;
            int base = (b * NCH + slice * 8) * 384 + h * 48 + col;
            float4 s = make_float4(0.f, 0.f, 0.f, 0.f);
#pragma unroll
            for (int k = 0; k < 8; k++) {
                float4 v = p[base + k * 384];
                s.x += v.x; s.y += v.y; s.z += v.z; s.w += v.w;
            }
            ((float4*)s_comb)[tid] = s;
        }
        if (warp == 15) {                          // Z reduce (64 partials)
            const float* zp = g_zpart + (b * Hh + h) * NCH;
            float z = zp[lane] + zp[lane + 32];
#pragma unroll
            for (int o = 16; o > 0; o >>= 1) z += __shfl_xor_sync(0xffffffffu, z, o);
            if (lane == 0) s_invz = 1.f / z;
        }
        __syncthreads();
        if (tid < 48) {
            float4 a = make_float4(0.f, 0.f, 0.f, 0.f);
#pragma unroll
            for (int sl = 0; sl < 8; sl++) {
                float4 v = ((const float4*)s_comb)[sl * 48 + tid];
                a.x += v.x; a.y += v.y; a.z += v.z; a.w += v.w;
            }
            ((float4*)s_xw)[tid] = a;
        }
        __syncthreads();

        // V projection: warps 0..11, 2 d's each; apply invZ; result in s_comb[0..23]
        if (warp < 12) {
#pragma unroll
            for (int dd = 0; dd < 2; dd++) {
                int d = warp * 2 + dd;
                const float* wv = Wqkv + (size_t)(2 * Cc + h * Dd + d) * Cc;
                float p = 0.f;
#pragma unroll
                for (int i = 0; i < 6; i++) p += s_xw[lane + 32 * i] * wv[lane + 32 * i];
#pragma unroll
                for (int o = 16; o > 0; o >>= 1) p += __shfl_down_sync(0xffffffffu, p, o);
                if (lane == 0) s_comb[d] = p * s_invz;
            }
        }
        __syncthreads();

        // yrow partial for this head (int64 fixed point => deterministic)
        if (tid < Cc) {
            const float* wp = Wproj + (size_t)tid * Cc + h * Dd;
            float s = 0.f;
#pragma unroll
            for (int d = 0; d < Dd; d++) s += s_comb[d] * wp[d];
            atomicAdd(&g_yfp[b * Cc + tid],
                      (unsigned long long)__float2ll_rn(s * FPSCALE));
        }
    }
    grid_sync();

    // =============== Phase E: convert + broadcast ===============
    {
        if (tid < Bsz * Cc) {
            long long v = (long long)g_yfp[tid];
            s_y[tid] = (float)v * FPINV + bproj[tid % Cc];
        }
        __syncthreads();
        const float4* sy4 = (const float4*)s_y;
        const int base = bid * 3072;               // 128 * 3072 = 393216 float4
#pragma unroll
        for (int k = 0; k < 6; k++) {
            int g = base + k * NT + tid;
            int r = g % 48;
            int b = (g >= Nn * 48) ? 1 : 0;
            out[g] = sy4[b * 48 + r];
        }
    }
}

extern "C" void kernel_launch(void* const* d_in, const int* in_sizes, int n_in,
                              void* d_out, int out_size) {
    const float* x     = (const float*)d_in[0];
    const float* Wqkv  = (const float*)d_in[1];
    const float* Wproj = (const float*)d_in[2];
    const float* bproj = (const float*)d_in[3];
    const float* scale = (const float*)d_in[4];

    k_pre<<<3, 512>>>(Wqkv);
    fused_kernel<<<NBLK, NT>>>(x, Wqkv, Wproj, bproj, scale, (float4*)d_out);
}

// round 7
// speedup vs baseline: 1.3908x; 1.0122x over previous
#include <cuda_runtime.h>

#define Bsz 2
#define Nn  4096
#define Cc  192
#define Hh  8
#define Dd  24
#define JCH 64                  // j-rows per task (one block per SM, uniform)
#define NCH 64                  // chunks per batch
#define NBLK 128
#define NT   512

#define FPSCALE 4194304.0f      // 2^22
#define FPINV   (1.0f / 4194304.0f)

// Scratch (__device__ globals; no allocations allowed)
__device__ float g_wksum[Hh * Cc];
__device__ unsigned long long g_Ufp[Bsz * Cc * Hh];   // [b][t'*8 + h], 3072
__device__ unsigned long long g_zfp[Bsz * Hh];        // 16
__device__ unsigned int g_ac_done = 0;

// ---------------------------------------------------------------------------
// Prelude: wksum; zero fixed-point accumulators + flag. (graph edge orders this)
// ---------------------------------------------------------------------------
__global__ void k_pre(const float* __restrict__ Wqkv) {
    int gid = blockIdx.x * 512 + threadIdx.x;          // 0..1535
    g_Ufp[gid] = 0ull;
    g_Ufp[gid + 1536] = 0ull;
    if (gid < Bsz * Hh) g_zfp[gid] = 0ull;
    if (gid == 0) g_ac_done = 0;
    int h = gid / Cc, c = gid - h * Cc;
    const float* base = Wqkv + (size_t)(Cc + h * Dd) * Cc + c;
    float s = 0.f;
#pragma unroll
    for (int d = 0; d < Dd; d++) s += base[(size_t)d * Cc];
    g_wksum[gid] = s;
}

// ---------------------------------------------------------------------------
__global__ __launch_bounds__(NT, 1)
void fused_kernel(const float* __restrict__ x,
                  const float* __restrict__ Wqkv,
                  const float* __restrict__ Wproj,
                  const float* __restrict__ bproj,
                  const float* __restrict__ scale,
                  float4* __restrict__ out) {
    __shared__ __align__(16) float s_ws[Hh * Cc];     // 1536
    __shared__ float s_e[Hh * JCH];                   // 512
    __shared__ __align__(16) float s_comb[Hh * Cc];   // 1536 (chunk xw)
    __shared__ __align__(16) float s_ov[Cc];          // 192 (chunk ovu partial)
    __shared__ float s_invz[Bsz * Hh];                // 16
    __shared__ __align__(16) float s_y[Bsz * Cc];     // 384

    const int tid  = threadIdx.x;
    const int bid  = blockIdx.x;
    const int warp = tid >> 5;
    const int lane = tid & 31;

    const int b     = bid >> 6;                       // 64 chunks per batch
    const int chunk = bid & 63;
    const int j0    = chunk * JCH;

    // ---- stage wksum ----
    if (tid < 384) ((float4*)s_ws)[tid] = ((const float4*)g_wksum)[tid];
    __syncthreads();

    // ---- e for 64 rows: 16 warps x 4 rows ----
    {
        const float sc = __ldg(scale);
#pragma unroll
        for (int r = 0; r < 4; r++) {
            const int jj = warp * 4 + r;
            const float* xr = x + (size_t)(b * Nn + j0 + jj) * Cc;
            float xv[6];
#pragma unroll
            for (int i = 0; i < 6; i++) xv[i] = xr[lane + 32 * i];
#pragma unroll
            for (int h = 0; h < Hh; h++) {
                float p = 0.f;
#pragma unroll
                for (int i = 0; i < 6; i++) p += xv[i] * s_ws[h * Cc + lane + 32 * i];
#pragma unroll
                for (int o = 16; o > 0; o >>= 1) p += __shfl_down_sync(0xffffffffu, p, o);
                if (lane == 0) s_e[h * JCH + jj] = __expf(p * sc);
            }
        }
    }
    __syncthreads();

    // ---- xw partial (threads 0..383) + Z fixed-point atomics (warps 12..15) ----
    {
        const int jg = tid / Cc;
        const int c  = tid - jg * Cc;
        float acc[Hh];
#pragma unroll
        for (int h = 0; h < Hh; h++) acc[h] = 0.f;

        if (tid < 2 * Cc) {
            const float* xp = x + ((size_t)(b * Nn + j0 + jg * 32)) * Cc + c;
#pragma unroll 8
            for (int q = 0; q < 32; q++) {
                float xv = xp[(size_t)q * Cc];       // L1-hot
                int wj = jg * 32 + q;
#pragma unroll
                for (int h = 0; h < Hh; h++) acc[h] += s_e[h * JCH + wj] * xv;
            }
        } else if (warp >= 12) {                      // Z partial -> global fp atomic
            int h = (warp - 12) * 2 + (lane >> 4);
            int l = lane & 15;
            const float* eh = s_e + h * JCH;
            float z = eh[l] + eh[16 + l] + eh[32 + l] + eh[48 + l];
#pragma unroll
            for (int o = 8; o > 0; o >>= 1) z += __shfl_xor_sync(0xffffffffu, z, o);
            if (l == 0)
                atomicAdd(&g_zfp[b * Hh + h],
                          (unsigned long long)__float2ll_rn(z * FPSCALE));
        }
        __syncthreads();
        if (jg == 1) {
#pragma unroll
            for (int h = 0; h < Hh; h++) s_comb[h * Cc + c] = acc[h];
        }
        __syncthreads();
        if (jg == 0) {
#pragma unroll
            for (int h = 0; h < Hh; h++) s_comb[h * Cc + c] += acc[h];
        }
    }
    __syncthreads();

    // ---- ovu partial: 192 dots of 192 (16 warps x 12 t) ----
    {
#pragma unroll
        for (int r = 0; r < 12; r++) {
            const int t = warp * 12 + r;              // 0..191
            const int h = t / Dd;
            const float* wv = Wqkv + (size_t)(2 * Cc + t) * Cc;
            const float* xwh = s_comb + h * Cc;
            float p = 0.f;
#pragma unroll
            for (int i = 0; i < 6; i++) p += xwh[lane + 32 * i] * wv[lane + 32 * i];
#pragma unroll
            for (int o = 16; o > 0; o >>= 1) p += __shfl_down_sync(0xffffffffu, p, o);
            if (lane == 0) s_ov[t] = p;
        }
    }
    __syncthreads();

    // ---- U partial: o = t'*8 + h; 3 outputs/thread; fixed-point atomics ----
    {
#pragma unroll
        for (int k = 0; k < 3; k++) {
            int o  = tid + k * NT;                    // 0..1535
            int tp = o >> 3, h = o & 7;
            const float4* wp = (const float4*)(Wproj + (size_t)tp * Cc + h * Dd);
            const float4* ov = (const float4*)(s_ov + h * Dd);
            float s = 0.f;
#pragma unroll
            for (int q = 0; q < 6; q++) {
                float4 w4 = wp[q], o4 = ov[q];
                s += w4.x * o4.x + w4.y * o4.y + w4.z * o4.z + w4.w * o4.w;
            }
            atomicAdd(&g_Ufp[b * 1536 + o],
                      (unsigned long long)__float2ll_rn(s * FPSCALE));
        }
    }
    __threadfence();
    __syncthreads();
    if (tid == 0) atomicAdd(&g_ac_done, 1u);

    // ---- single arrival-spin sync ----
    if (tid == 0) {
        volatile unsigned int* p = &g_ac_done;
        while (*p < (unsigned)NBLK) __nanosleep(64);
    }
    __syncthreads();
    __threadfence();

    // ---- every block redundantly computes y (pure function of U,Z => deterministic) ----
    if (tid < Bsz * Hh)
        s_invz[tid] = 1.f / ((float)(long long)g_zfp[tid] * FPINV);
    __syncthreads();
    if (tid < Bsz * Cc) {
        const int b2 = tid / Cc, tp = tid - b2 * Cc;
        const unsigned long long* up = g_Ufp + b2 * 1536 + tp * 8;
        float s = bproj[tp];
#pragma unroll
        for (int h = 0; h < Hh; h++)
            s += s_invz[b2 * Hh + h] * ((float)(long long)up[h] * FPINV);
        s_y[tid] = s;
    }
    __syncthreads();

    // ---- broadcast: 128 * 3072 = 393216 float4 ----
    {
        const float4* sy4 = (const float4*)s_y;
        const int base = bid * 3072;
#pragma unroll
        for (int k = 0; k < 6; k++) {
            int g = base + k * NT + tid;
            int r = g % 48;
            int bb = (g >= Nn * 48) ? 1 : 0;
            out[g] = sy4[bb * 48 + r];
        }
    }
}

extern "C" void kernel_launch(void* const* d_in, const int* in_sizes, int n_in,
                              void* d_out, int out_size) {
    const float* x     = (const float*)d_in[0];
    const float* Wqkv  = (const float*)d_in[1];
    const float* Wproj = (const float*)d_in[2];
    const float* bproj = (const float*)d_in[3];
    const float* scale = (const float*)d_in[4];

    k_pre<<<3, 512>>>(Wqkv);
    fused_kernel<<<NBLK, NT>>>(x, Wqkv, Wproj, bproj, scale, (float4*)d_out);
}